// round 6
// baseline (speedup 1.0000x reference)
#include <cuda_runtime.h>
#include <cuda_bf16.h>

#define N 8192
#define T 128                    // threads per block
#define R 8                      // i's per thread (register tile)
#define I_PER_BLOCK (T * R)      // 1024
#define I_ROWS (N / I_PER_BLOCK) // 8
#define JC 32                    // j-chunks
#define JCHUNK (N / JC)          // 256
#define GRID (I_ROWS * JC)       // 256 blocks
#define EPI 32                   // last-32 arrivals run the epilogue
#define I_PER_EPI (N / EPI)      // 256 i's per epilogue block

__device__ float g_part[JC * N];   // [jc][i] partial risk sums: 1 MB
__device__ float g_bpart[EPI];     // epilogue per-slice loss partials
__device__ int   g_sync;           // arrival counter   (zero-init, self-reset)
__device__ int   g_count2;         // epilogue-done counter (zero-init, self-reset)

// One launch. Stage 1: tiled pairwise risk-sum partials. Then each block
// takes a ticket; only the last EPI arrivals wait for everyone (bounded
// spinners => deadlock-free at ANY occupancy) and run stage 2.
__global__ void __launch_bounds__(T, 8)
cox_fused_kernel(const float* __restrict__ hazard,
                 const float* __restrict__ time,
                 const float* __restrict__ censor,
                 float* __restrict__ out)
{
    __shared__ float2 te[JCHUNK];
    const int tid  = threadIdx.x;
    const int irow = blockIdx.x & (I_ROWS - 1);
    const int jc   = blockIdx.x >> 3;             // I_ROWS == 8

    // ---- Stage 1: (1024 i) x (256 j) tile ----
    for (int t = tid; t < JCHUNK; t += T) {
        const int j = jc * JCHUNK + t;
        te[t] = make_float2(time[j], expf(hazard[j]));
    }

    const int ibase = irow * I_PER_BLOCK + tid;
    float ti[R], acc[R];
#pragma unroll
    for (int r = 0; r < R; ++r) {
        ti[r]  = time[ibase + r * T];
        acc[r] = 0.0f;
    }
    __syncthreads();

#pragma unroll 8
    for (int j = 0; j < JCHUNK; ++j) {
        const float2 v = te[j];                   // warp broadcast LDS.64
#pragma unroll
        for (int r = 0; r < R; ++r)
            if (v.x >= ti[r]) acc[r] += v.y;      // FSETP + @P FADD
    }

#pragma unroll
    for (int r = 0; r < R; ++r)
        g_part[jc * N + ibase + r * T] = acc[r];  // coalesced

    // ---- Ticketing: only the last EPI arrivals continue ----
    __shared__ int ticket_s;
    if (tid == 0) {
        __threadfence();                          // publish this block's g_part
        ticket_s = atomicAdd(&g_sync, 1);
    }
    __syncthreads();
    const int ticket = ticket_s;
    if (ticket < GRID - EPI) return;              // uniform per block

    const int slice = ticket - (GRID - EPI);      // 0..EPI-1

    if (tid == 0) {
        while (atomicAdd(&g_sync, 0) < GRID)      // wait for all stage-1 writes
            __nanosleep(32);
        __threadfence();                          // acquire g_part
    }
    __syncthreads();

    // ---- Stage 2: this slice owns i in [slice*256, slice*256+256) ----
    float c = 0.0f;
#pragma unroll
    for (int s = 0; s < I_PER_EPI / T; ++s) {     // 2 i's per thread
        const int i = slice * I_PER_EPI + s * T + tid;
        float rs = 0.0f;
#pragma unroll
        for (int k = 0; k < JC; ++k)
            rs += g_part[k * N + i];              // coalesced, L2-resident
        c += (hazard[i] - logf(rs)) * censor[i];
    }

    __shared__ float sred[T];
    sred[tid] = c;
    __syncthreads();
    if (tid < 64) sred[tid] += sred[tid + 64];
    __syncthreads();
    if (tid < 32) {
        float v = sred[tid] + sred[tid + 32];
#pragma unroll
        for (int o = 16; o > 0; o >>= 1)
            v += __shfl_down_sync(0xffffffffu, v, o);
        if (tid == 0) {
            g_bpart[slice] = v;
            __threadfence();
            if (atomicAdd(&g_count2, 1) == EPI - 1) {
                __threadfence();                  // acquire all g_bpart
                float tot = 0.0f;
#pragma unroll
                for (int b = 0; b < EPI; ++b)     // fixed order -> deterministic
                    tot += g_bpart[b];
                out[0] = -tot / (float)N;
                g_sync   = 0;                     // all spinners already passed
                g_count2 = 0;                     // ready for next replay
            }
        }
    }
}

extern "C" void kernel_launch(void* const* d_in, const int* in_sizes, int n_in,
                              void* d_out, int out_size)
{
    const float* hazard = (const float*)d_in[0];
    const float* time_  = (const float*)d_in[1];
    const float* censor = (const float*)d_in[2];
    float* out = (float*)d_out;

    cox_fused_kernel<<<GRID, T>>>(hazard, time_, censor, out);
}

// round 7
// speedup vs baseline: 1.0078x; 1.0078x over previous
#include <cuda_runtime.h>
#include <cuda_bf16.h>

#define N 8192
#define T 128                    // threads per block
#define R 8                      // i's per thread (register tile)
#define I_PER_BLOCK (T * R)      // 1024
#define I_ROWS (N / I_PER_BLOCK) // 8
#define JC 64                    // j-chunks
#define JCHUNK (N / JC)          // 128
#define GRID (I_ROWS * JC)       // 512 blocks

__device__ float g_risk[N];        // accumulated risk sums (zero-init; reset by epilogue)
__device__ int   g_sync;           // arrival counter (zero-init; reset by epilogue)

// One launch, no spinning anywhere. Each block computes a (1024 i x 128 j)
// tile and atomically folds it into g_risk. The LAST block to arrive (ticket
// == GRID-1) knows all other blocks have fenced and finished, so it runs the
// tiny epilogue immediately: per-i loss, total, reset state for next replay.
__global__ void __launch_bounds__(T, 8)
cox_fused_kernel(const float* __restrict__ hazard,
                 const float* __restrict__ time,
                 const float* __restrict__ censor,
                 float* __restrict__ out)
{
    __shared__ float2 te[JCHUNK];
    const int tid  = threadIdx.x;
    const int irow = blockIdx.x & (I_ROWS - 1);
    const int jc   = blockIdx.x >> 3;             // I_ROWS == 8

    // ---- Stage 1: (1024 i) x (128 j) tile ----
    if (tid < JCHUNK) {
        const int j = jc * JCHUNK + tid;
        te[tid] = make_float2(time[j], expf(hazard[j]));
    }

    const int ibase = irow * I_PER_BLOCK + tid;
    float ti[R], acc[R];
#pragma unroll
    for (int r = 0; r < R; ++r) {
        ti[r]  = time[ibase + r * T];
        acc[r] = 0.0f;
    }
    __syncthreads();

#pragma unroll 8
    for (int j = 0; j < JCHUNK; ++j) {
        const float2 v = te[j];                   // warp broadcast LDS.64
#pragma unroll
        for (int r = 0; r < R; ++r)
            if (v.x >= ti[r]) acc[r] += v.y;      // FSETP + @P FADD
    }

#pragma unroll
    for (int r = 0; r < R; ++r)
        atomicAdd(&g_risk[ibase + r * T], acc[r]); // spread REDG, no hot spot

    // ---- Ticket: last arrival == everyone else already done ----
    __shared__ int ticket_s;
    __syncthreads();                              // all atomics issued
    if (tid == 0) {
        __threadfence();                          // publish our adds
        ticket_s = atomicAdd(&g_sync, 1);
    }
    __syncthreads();
    if (ticket_s != GRID - 1) return;             // no waiting, ever

    // ---- Epilogue (single block, all prior work visible) ----
    __threadfence();                              // acquire all g_risk adds

    float c = 0.0f;
#pragma unroll
    for (int s = 0; s < N / T; ++s) {             // 64 i's per thread
        const int i = s * T + tid;
        const float rs = g_risk[i];
        c += (hazard[i] - logf(rs)) * censor[i];
        g_risk[i] = 0.0f;                         // reset for next replay
    }

    __shared__ float sred[T];
    sred[tid] = c;
    __syncthreads();
    if (tid < 64) sred[tid] += sred[tid + 64];
    __syncthreads();
    if (tid < 32) {
        float v = sred[tid] + sred[tid + 32];
#pragma unroll
        for (int o = 16; o > 0; o >>= 1)
            v += __shfl_down_sync(0xffffffffu, v, o);
        if (tid == 0) {
            out[0] = -v / (float)N;
            g_sync = 0;                           // safe: all blocks already ticketed
        }
    }
}

extern "C" void kernel_launch(void* const* d_in, const int* in_sizes, int n_in,
                              void* d_out, int out_size)
{
    const float* hazard = (const float*)d_in[0];
    const float* time_  = (const float*)d_in[1];
    const float* censor = (const float*)d_in[2];
    float* out = (float*)d_out;

    cox_fused_kernel<<<GRID, T>>>(hazard, time_, censor, out);
}